// round 5
// baseline (speedup 1.0000x reference)
#include <cuda_runtime.h>
#include <cuda_bf16.h>

#define H 128
#define NN 65536
#define GG 32768
#define EE 600000

// Scratch (static __device__ — no runtime allocation)
__device__ __align__(16) float g_nf[(size_t)NN * H];    // node MLP output     (32 MB)
__device__ __align__(16) float g_ef[(size_t)EE * H];    // edge-feature output (307 MB)
__device__ __align__(16) float g_agg[(size_t)GG * H];   // scatter accumulator (16 MB)
__device__ __align__(16) float g_cnt[GG];               // per-grid-point counts

__device__ __forceinline__ float silu_f(float x) {
    return x / (1.0f + __expf(-x));
}

// ---------------------------------------------------------------------------
// Zero the aggregation buffers (graph-capturable; runs every launch)
// ---------------------------------------------------------------------------
__global__ void zero_kernel() {
    size_t i = blockIdx.x * (size_t)blockDim.x + threadIdx.x;
    size_t stride = (size_t)gridDim.x * blockDim.x;
    size_t total4 = (size_t)GG * H / 4;
    float4 z = make_float4(0.f, 0.f, 0.f, 0.f);
    for (size_t p = i; p < total4; p += stride)
        reinterpret_cast<float4*>(g_agg)[p] = z;
    if (i < GG) g_cnt[i] = 0.f;
}

// ---------------------------------------------------------------------------
// Generic 2-layer MLP, Din = H = 128.  Thread j = output column j.
// R rows per block held in registers; x tile + hidden tile in smem.
// ---------------------------------------------------------------------------
template <int R>
__global__ __launch_bounds__(H) void mlp128_kernel(
    const float* __restrict__ x,
    const float* __restrict__ w1, const float* __restrict__ b1,
    const float* __restrict__ w2, const float* __restrict__ b2,
    float* __restrict__ out)
{
    __shared__ __align__(16) float xs[R][H];
    __shared__ __align__(16) float hs[R][H];
    const int base = blockIdx.x * R;
    const int j = threadIdx.x;

    // Coalesced tile load
    const float4* src4 = reinterpret_cast<const float4*>(x + (size_t)base * H);
    float4* dst4 = reinterpret_cast<float4*>(&xs[0][0]);
    #pragma unroll
    for (int i = j; i < R * H / 4; i += H) dst4[i] = src4[i];
    __syncthreads();

    float acc[R];
    float bb = b1[j];
    #pragma unroll
    for (int r = 0; r < R; r++) acc[r] = bb;
    #pragma unroll 4
    for (int k = 0; k < H; k++) {
        float w = w1[k * H + j];
        #pragma unroll
        for (int r = 0; r < R; r++) acc[r] = fmaf(xs[r][k], w, acc[r]);
    }
    #pragma unroll
    for (int r = 0; r < R; r++) hs[r][j] = silu_f(acc[r]);
    __syncthreads();

    bb = b2[j];
    #pragma unroll
    for (int r = 0; r < R; r++) acc[r] = bb;
    #pragma unroll 4
    for (int k = 0; k < H; k++) {
        float w = w2[k * H + j];
        #pragma unroll
        for (int r = 0; r < R; r++) acc[r] = fmaf(hs[r][k], w, acc[r]);
    }
    #pragma unroll
    for (int r = 0; r < R; r++) out[(size_t)(base + r) * H + j] = acc[r];
}

// ---------------------------------------------------------------------------
// Edge-feature MLP: edge_attr[e] = [node_pos[src], grid_pos[tgt]] (6) -> ef[e] (128)
// ---------------------------------------------------------------------------
template <int R>
__global__ __launch_bounds__(H) void edge_mlp_kernel(
    const int* __restrict__ eidx,                // [2, E] int32
    const float* __restrict__ node_pos,          // [N, 3]
    const float* __restrict__ grid_pos,          // [G, 3]
    const float* __restrict__ w1, const float* __restrict__ b1,   // [6,128]
    const float* __restrict__ w2, const float* __restrict__ b2)   // [128,128]
{
    __shared__ float ea[R][6];
    __shared__ __align__(16) float hs[R][H];
    const int base = blockIdx.x * R;
    const int j = threadIdx.x;

    if (j < R * 6) {
        int r = j / 6, c = j % 6;
        int e = base + r;
        float v;
        if (c < 3) { int s = eidx[e];        v = node_pos[(size_t)s * 3 + c]; }
        else       { int t = eidx[EE + e];   v = grid_pos[(size_t)t * 3 + (c - 3)]; }
        ea[r][c] = v;
    }
    __syncthreads();

    float acc[R];
    float bb = b1[j];
    #pragma unroll
    for (int r = 0; r < R; r++) acc[r] = bb;
    #pragma unroll
    for (int k = 0; k < 6; k++) {
        float w = w1[k * H + j];
        #pragma unroll
        for (int r = 0; r < R; r++) acc[r] = fmaf(ea[r][k], w, acc[r]);
    }
    #pragma unroll
    for (int r = 0; r < R; r++) hs[r][j] = silu_f(acc[r]);
    __syncthreads();

    bb = b2[j];
    #pragma unroll
    for (int r = 0; r < R; r++) acc[r] = bb;
    #pragma unroll 4
    for (int k = 0; k < H; k++) {
        float w = w2[k * H + j];
        #pragma unroll
        for (int r = 0; r < R; r++) acc[r] = fmaf(hs[r][k], w, acc[r]);
    }
    #pragma unroll
    for (int r = 0; r < R; r++) g_ef[(size_t)(base + r) * H + j] = acc[r];
}

// ---------------------------------------------------------------------------
// Per-target edge counts
// ---------------------------------------------------------------------------
__global__ void count_kernel(const int* __restrict__ eidx) {
    int e = blockIdx.x * blockDim.x + threadIdx.x;
    if (e < EE) {
        int t = eidx[EE + e];
        atomicAdd(&g_cnt[t], 1.0f);
    }
}

// ---------------------------------------------------------------------------
// Message MLP ([nf[src], ef] (256) -> 128) + scatter-add via red.global.v4
// ---------------------------------------------------------------------------
template <int R>
__global__ __launch_bounds__(H) void msg_kernel(const int* __restrict__ eidx,
    const float* __restrict__ w1, const float* __restrict__ b1,   // [256,128]
    const float* __restrict__ w2, const float* __restrict__ b2)   // [128,128]
{
    __shared__ __align__(16) float xin[R][2 * H];   // 16 KB
    __shared__ __align__(16) float hs[R][H];        // 8 KB
    __shared__ int tg[R];
    const int base = blockIdx.x * R;
    const int j = threadIdx.x;

    #pragma unroll
    for (int r = 0; r < R; r++) {
        int s = eidx[base + r];                       // uniform within block-row
        xin[r][j]     = g_nf[(size_t)s * H + j];      // L2-resident gather
        xin[r][H + j] = g_ef[(size_t)(base + r) * H + j];
    }
    if (j < R) tg[j] = eidx[EE + base + j];
    __syncthreads();

    float acc[R];
    float bb = b1[j];
    #pragma unroll
    for (int r = 0; r < R; r++) acc[r] = bb;
    #pragma unroll 2
    for (int k = 0; k < 2 * H; k++) {
        float w = w1[k * H + j];
        #pragma unroll
        for (int r = 0; r < R; r++) acc[r] = fmaf(xin[r][k], w, acc[r]);
    }
    #pragma unroll
    for (int r = 0; r < R; r++) hs[r][j] = silu_f(acc[r]);
    __syncthreads();

    bb = b2[j];
    #pragma unroll
    for (int r = 0; r < R; r++) acc[r] = bb;
    #pragma unroll 4
    for (int k = 0; k < H; k++) {
        float w = w2[k * H + j];
        #pragma unroll
        for (int r = 0; r < R; r++) acc[r] = fmaf(hs[r][k], w, acc[r]);
    }

    __syncthreads();                       // everyone done reading hs
    #pragma unroll
    for (int r = 0; r < R; r++) hs[r][j] = acc[r];
    __syncthreads();

    // Vector atomics: R edges x 32 float4 chunks, 128 threads -> 4 iterations
    for (int t = j; t < R * 32; t += H) {
        int r = t >> 5;
        int c = (t & 31) * 4;
        float4 v = *reinterpret_cast<float4*>(&hs[r][c]);
        float* dst = &g_agg[(size_t)tg[r] * H + c];
        asm volatile("red.global.add.v4.f32 [%0], {%1,%2,%3,%4};"
                     :: "l"(dst), "f"(v.x), "f"(v.y), "f"(v.z), "f"(v.w)
                     : "memory");
    }
}

// ---------------------------------------------------------------------------
// Update MLP on agg/counts -> final output [G,128]
// ---------------------------------------------------------------------------
template <int R>
__global__ __launch_bounds__(H) void update_mlp_kernel(
    const float* __restrict__ w1, const float* __restrict__ b1,
    const float* __restrict__ w2, const float* __restrict__ b2,
    float* __restrict__ out)
{
    __shared__ __align__(16) float xs[R][H];
    __shared__ __align__(16) float hs[R][H];
    __shared__ float sc[R];
    const int base = blockIdx.x * R;
    const int j = threadIdx.x;

    if (j < R) {
        float c = g_cnt[base + j];
        sc[j] = 1.0f / fmaxf(c, 1.0f);
    }
    __syncthreads();

    const float4* src4 = reinterpret_cast<const float4*>(g_agg + (size_t)base * H);
    #pragma unroll
    for (int i = j; i < R * H / 4; i += H) {
        int r = i / (H / 4);
        float4 v = src4[i];
        float s = sc[r];
        v.x *= s; v.y *= s; v.z *= s; v.w *= s;
        reinterpret_cast<float4*>(&xs[0][0])[i] = v;
    }
    __syncthreads();

    float acc[R];
    float bb = b1[j];
    #pragma unroll
    for (int r = 0; r < R; r++) acc[r] = bb;
    #pragma unroll 4
    for (int k = 0; k < H; k++) {
        float w = w1[k * H + j];
        #pragma unroll
        for (int r = 0; r < R; r++) acc[r] = fmaf(xs[r][k], w, acc[r]);
    }
    #pragma unroll
    for (int r = 0; r < R; r++) hs[r][j] = silu_f(acc[r]);
    __syncthreads();

    bb = b2[j];
    #pragma unroll
    for (int r = 0; r < R; r++) acc[r] = bb;
    #pragma unroll 4
    for (int k = 0; k < H; k++) {
        float w = w2[k * H + j];
        #pragma unroll
        for (int r = 0; r < R; r++) acc[r] = fmaf(hs[r][k], w, acc[r]);
    }
    #pragma unroll
    for (int r = 0; r < R; r++) out[(size_t)(base + r) * H + j] = acc[r];
}

// ---------------------------------------------------------------------------
// Launch
// ---------------------------------------------------------------------------
extern "C" void kernel_launch(void* const* d_in, const int* in_sizes, int n_in,
                              void* d_out, int out_size) {
    const float* node_features = (const float*)d_in[0];
    const float* node_pos      = (const float*)d_in[1];
    const float* grid_pos      = (const float*)d_in[2];
    const int*   edge_index    = (const int*)d_in[3];   // int32 (JAX default)
    const float* nm_w1 = (const float*)d_in[4];
    const float* nm_b1 = (const float*)d_in[5];
    const float* nm_w2 = (const float*)d_in[6];
    const float* nm_b2 = (const float*)d_in[7];
    const float* em_w1 = (const float*)d_in[8];
    const float* em_b1 = (const float*)d_in[9];
    const float* em_w2 = (const float*)d_in[10];
    const float* em_b2 = (const float*)d_in[11];
    const float* mm_w1 = (const float*)d_in[12];
    const float* mm_b1 = (const float*)d_in[13];
    const float* mm_w2 = (const float*)d_in[14];
    const float* mm_b2 = (const float*)d_in[15];
    const float* um_w1 = (const float*)d_in[16];
    const float* um_b1 = (const float*)d_in[17];
    const float* um_w2 = (const float*)d_in[18];
    const float* um_b2 = (const float*)d_in[19];
    float* out = (float*)d_out;

    constexpr int R = 16;

    float* nf_ptr;  cudaGetSymbolAddress((void**)&nf_ptr, g_nf);

    zero_kernel<<<1024, 256>>>();

    // node MLP: [N,128] -> [N,128]
    mlp128_kernel<R><<<NN / R, H>>>(node_features, nm_w1, nm_b1, nm_w2, nm_b2, nf_ptr);

    // edge-feature MLP: [E,6] -> [E,128]
    edge_mlp_kernel<R><<<EE / R, H>>>(edge_index, node_pos, grid_pos,
                                      em_w1, em_b1, em_w2, em_b2);

    // per-target counts
    count_kernel<<<(EE + 255) / 256, 256>>>(edge_index);

    // message MLP + scatter-add
    msg_kernel<R><<<EE / R, H>>>(edge_index, mm_w1, mm_b1, mm_w2, mm_b2);

    // update MLP on mean-aggregated features -> output [G,128]
    update_mlp_kernel<R><<<GG / R, H>>>(um_w1, um_b1, um_w2, um_b2, out);
}

// round 7
// speedup vs baseline: 1.4300x; 1.4300x over previous
#include <cuda_runtime.h>

#define H  128
#define NN 65536
#define GG 32768
#define EE 600000
#define RT 32          // rows (edges/nodes) per tile
#define R2T 16         // row pairs per tile
#define RP 36          // padded tile row length in floats (144B, 16B-aligned rows)

// Scratch (static __device__ — no runtime allocation)
__device__ __align__(16) float g_nf2[(size_t)NN * H];   // nf @ mm_w1_top  (32 MB)
__device__ __align__(16) float g_agg[(size_t)GG * H];   // scatter accumulator (16 MB)
__device__ float g_cnt[GG];

// ---------------------------------------------------------------------------
// Packed f32x2 helpers (FFMA2 path — sm_103a)
// ---------------------------------------------------------------------------
__device__ __forceinline__ unsigned long long pack2(float lo, float hi) {
    unsigned long long r;
    asm("mov.b64 %0, {%1,%2};" : "=l"(r) : "f"(lo), "f"(hi));
    return r;
}
__device__ __forceinline__ void unpack2(unsigned long long v, float& lo, float& hi) {
    asm("mov.b64 {%0,%1}, %2;" : "=f"(lo), "=f"(hi) : "l"(v));
}
__device__ __forceinline__ void ffma2(unsigned long long& d,
                                      unsigned long long a, unsigned long long b) {
    asm("fma.rn.f32x2 %0, %1, %2, %0;" : "+l"(d) : "l"(a), "l"(b));
}
__device__ __forceinline__ float silu_f(float x) {
    return x / (1.0f + __expf(-x));
}

// ---------------------------------------------------------------------------
// Core packed GEMM:  acc[pair] += A[k][row-pair] * W[k][j]  over k=0..KK-1
// A is a [KK][RP] smem tile (row-pairs contiguous); W is [KK,H] row-major.
// ---------------------------------------------------------------------------
template <int KK>
__device__ __forceinline__ void gemm_acc(const float* __restrict__ A,
                                         const float* __restrict__ W,
                                         int j, unsigned long long* acc) {
    #pragma unroll 4
    for (int k = 0; k < KK; k++) {
        float w = W[k * H + j];
        unsigned long long wp = pack2(w, w);
        const float* row = A + k * RP;
        #pragma unroll
        for (int q = 0; q < R2T / 2; q++) {           // 16B chunk = 2 row-pairs
            ulonglong2 v = *reinterpret_cast<const ulonglong2*>(row + 4 * q);
            ffma2(acc[2 * q],     v.x, wp);
            ffma2(acc[2 * q + 1], v.y, wp);
        }
    }
}

__device__ __forceinline__ void acc_init(unsigned long long* acc, float b) {
    unsigned long long bb = pack2(b, b);
    #pragma unroll
    for (int q = 0; q < R2T; q++) acc[q] = bb;
}

// store acc (optionally silu) into a [H][RP] tile at row j (paired layout)
__device__ __forceinline__ void acc_store_tile(unsigned long long* acc, float* dstRow,
                                               bool do_silu) {
    #pragma unroll
    for (int q = 0; q < R2T; q++) {
        float lo, hi;
        unpack2(acc[q], lo, hi);
        if (do_silu) { lo = silu_f(lo); hi = silu_f(hi); }
        *reinterpret_cast<unsigned long long*>(dstRow + 2 * q) = pack2(lo, hi);
    }
}

// ---------------------------------------------------------------------------
// Zero the aggregation buffers
// ---------------------------------------------------------------------------
__global__ void zero_kernel() {
    size_t i = blockIdx.x * (size_t)blockDim.x + threadIdx.x;
    size_t stride = (size_t)gridDim.x * blockDim.x;
    size_t total4 = (size_t)GG * H / 4;
    float4 z = make_float4(0.f, 0.f, 0.f, 0.f);
    for (size_t p = i; p < total4; p += stride)
        reinterpret_cast<float4*>(g_agg)[p] = z;
    if (i < GG) g_cnt[i] = 0.f;
}

// ---------------------------------------------------------------------------
// Node kernel: x -> silu(x@nm_w1+b1) -> @nm_w2+b2 -> @mm_w1_top  => g_nf2
// (nf itself is never needed downstream; only nf2 = nf @ mm_w1[:128] is.)
// ---------------------------------------------------------------------------
__global__ __launch_bounds__(H) void node_kernel(
    const float* __restrict__ x,
    const float* __restrict__ nm_w1, const float* __restrict__ nm_b1,
    const float* __restrict__ nm_w2, const float* __restrict__ nm_b2,
    const float* __restrict__ mm_w1)
{
    __shared__ __align__(16) float A[H][RP];
    __shared__ __align__(16) float B[H][RP];
    const int base = blockIdx.x * RT;
    const int j = threadIdx.x;

    #pragma unroll
    for (int r = 0; r < RT; r++)
        A[j][r] = x[(size_t)(base + r) * H + j];
    __syncthreads();

    unsigned long long acc[R2T];

    acc_init(acc, nm_b1[j]);
    gemm_acc<H>(&A[0][0], nm_w1, j, acc);
    acc_store_tile(acc, &B[j][0], true);
    __syncthreads();

    acc_init(acc, nm_b2[j]);
    gemm_acc<H>(&B[0][0], nm_w2, j, acc);
    acc_store_tile(acc, &A[j][0], false);      // nf tile (no activation)
    __syncthreads();

    acc_init(acc, 0.0f);                        // nf2 = nf @ mm_w1_top (no bias)
    gemm_acc<H>(&A[0][0], mm_w1, j, acc);
    #pragma unroll
    for (int q = 0; q < R2T; q++) {
        float lo, hi;
        unpack2(acc[q], lo, hi);
        g_nf2[(size_t)(base + 2 * q) * H + j]     = lo;
        g_nf2[(size_t)(base + 2 * q + 1) * H + j] = hi;
    }
}

// ---------------------------------------------------------------------------
// Per-target edge counts
// ---------------------------------------------------------------------------
__global__ void count_kernel(const int* __restrict__ eidx) {
    int e = blockIdx.x * blockDim.x + threadIdx.x;
    if (e < EE) atomicAdd(&g_cnt[eidx[EE + e]], 1.0f);
}

// ---------------------------------------------------------------------------
// Fused edge kernel (per 32-edge tile):
//   ea(6) -> h=silu(ea@em_w1+b)     [K=6]
//         -> ef=h@em_w2+b           [K=128]
//         -> m=silu(ef@mm_w1_bot + nf2[src] + mm_b1)   [K=128]
//         -> msg=m@mm_w2+b          [K=128]
//         -> red.global.add.v4 into g_agg[tgt]
// ---------------------------------------------------------------------------
__global__ __launch_bounds__(H) void edge_kernel(
    const int* __restrict__ eidx,
    const float* __restrict__ node_pos, const float* __restrict__ grid_pos,
    const float* __restrict__ em_w1, const float* __restrict__ em_b1,
    const float* __restrict__ em_w2, const float* __restrict__ em_b2,
    const float* __restrict__ mm_w1, const float* __restrict__ mm_b1,
    const float* __restrict__ mm_w2, const float* __restrict__ mm_b2)
{
    __shared__ __align__(16) float EA[6][RP];
    __shared__ __align__(16) float A[H][RP];
    __shared__ __align__(16) char  Braw[H * RP * 4];   // aliased: ef tile, then msg staging
    __shared__ int ssrc[RT], stgt[RT];

    float (*B)[RP]     = reinterpret_cast<float(*)[RP]>(Braw);      // [H][RP]
    float (*MS)[H + 4] = reinterpret_cast<float(*)[H + 4]>(Braw);   // [RT][132]

    const int base = blockIdx.x * RT;
    const int j = threadIdx.x;

    if (j < RT) {
        ssrc[j] = eidx[base + j];
        stgt[j] = eidx[EE + base + j];
    }
    __syncthreads();

    // 6*RT = 192 entries > 128 threads: MUST be a strided loop
    for (int t = j; t < 6 * RT; t += H) {
        int r = t / 6, c = t % 6;
        EA[c][r] = (c < 3) ? node_pos[(size_t)ssrc[r] * 3 + c]
                           : grid_pos[(size_t)stgt[r] * 3 + (c - 3)];
    }
    __syncthreads();

    unsigned long long acc[R2T];

    // L1: edge MLP hidden (K=6)
    acc_init(acc, em_b1[j]);
    gemm_acc<6>(&EA[0][0], em_w1, j, acc);
    acc_store_tile(acc, &A[j][0], true);
    __syncthreads();

    // L2: ef (K=128, no activation)
    acc_init(acc, em_b2[j]);
    gemm_acc<H>(&A[0][0], em_w2, j, acc);
    acc_store_tile(acc, &B[j][0], false);
    __syncthreads();

    // L3: message hidden = silu(ef@mm_w1_bot + nf2[src] + mm_b1)
    acc_init(acc, mm_b1[j]);
    gemm_acc<H>(&B[0][0], mm_w1 + (size_t)H * H, j, acc);
    #pragma unroll
    for (int q = 0; q < R2T; q++) {
        float lo, hi;
        unpack2(acc[q], lo, hi);
        lo += g_nf2[(size_t)ssrc[2 * q] * H + j];
        hi += g_nf2[(size_t)ssrc[2 * q + 1] * H + j];
        *reinterpret_cast<unsigned long long*>(&A[j][2 * q]) =
            pack2(silu_f(lo), silu_f(hi));
    }
    __syncthreads();                    // all B reads done; MS may now alias B

    // L4: msg = m @ mm_w2 + mm_b2  -> MS[r][j]
    acc_init(acc, mm_b2[j]);
    gemm_acc<H>(&A[0][0], mm_w2, j, acc);
    #pragma unroll
    for (int q = 0; q < R2T; q++) {
        float lo, hi;
        unpack2(acc[q], lo, hi);
        MS[2 * q][j]     = lo;
        MS[2 * q + 1][j] = hi;
    }
    __syncthreads();

    // Scatter: 32 edges x 32 float4 chunks via vector atomics
    #pragma unroll
    for (int t = j; t < RT * 32; t += H) {
        int r = t >> 5;
        int c = (t & 31) * 4;
        float4 v = *reinterpret_cast<float4*>(&MS[r][c]);
        float* dst = &g_agg[(size_t)stgt[r] * H + c];
        asm volatile("red.global.add.v4.f32 [%0], {%1,%2,%3,%4};"
                     :: "l"(dst), "f"(v.x), "f"(v.y), "f"(v.z), "f"(v.w)
                     : "memory");
    }
}

// ---------------------------------------------------------------------------
// Update MLP on mean-aggregated features -> output [G,128]
// ---------------------------------------------------------------------------
__global__ __launch_bounds__(H) void update_kernel(
    const float* __restrict__ w1, const float* __restrict__ b1,
    const float* __restrict__ w2, const float* __restrict__ b2,
    float* __restrict__ out)
{
    __shared__ __align__(16) float A[H][RP];
    __shared__ __align__(16) float B[H][RP];
    __shared__ float sc[RT];
    const int base = blockIdx.x * RT;
    const int j = threadIdx.x;

    if (j < RT) {
        float c = g_cnt[base + j];
        sc[j] = 1.0f / fmaxf(c, 1.0f);
    }
    __syncthreads();

    #pragma unroll
    for (int r = 0; r < RT; r++)
        A[j][r] = g_agg[(size_t)(base + r) * H + j] * sc[r];
    __syncthreads();

    unsigned long long acc[R2T];

    acc_init(acc, b1[j]);
    gemm_acc<H>(&A[0][0], w1, j, acc);
    acc_store_tile(acc, &B[j][0], true);
    __syncthreads();

    acc_init(acc, b2[j]);
    gemm_acc<H>(&B[0][0], w2, j, acc);
    #pragma unroll
    for (int q = 0; q < R2T; q++) {
        float lo, hi;
        unpack2(acc[q], lo, hi);
        out[(size_t)(base + 2 * q) * H + j]     = lo;
        out[(size_t)(base + 2 * q + 1) * H + j] = hi;
    }
}

// ---------------------------------------------------------------------------
// Launch
// ---------------------------------------------------------------------------
extern "C" void kernel_launch(void* const* d_in, const int* in_sizes, int n_in,
                              void* d_out, int out_size) {
    const float* node_features = (const float*)d_in[0];
    const float* node_pos      = (const float*)d_in[1];
    const float* grid_pos      = (const float*)d_in[2];
    const int*   edge_index    = (const int*)d_in[3];
    const float* nm_w1 = (const float*)d_in[4];
    const float* nm_b1 = (const float*)d_in[5];
    const float* nm_w2 = (const float*)d_in[6];
    const float* nm_b2 = (const float*)d_in[7];
    const float* em_w1 = (const float*)d_in[8];
    const float* em_b1 = (const float*)d_in[9];
    const float* em_w2 = (const float*)d_in[10];
    const float* em_b2 = (const float*)d_in[11];
    const float* mm_w1 = (const float*)d_in[12];
    const float* mm_b1 = (const float*)d_in[13];
    const float* mm_w2 = (const float*)d_in[14];
    const float* mm_b2 = (const float*)d_in[15];
    const float* um_w1 = (const float*)d_in[16];
    const float* um_b1 = (const float*)d_in[17];
    const float* um_w2 = (const float*)d_in[18];
    const float* um_b2 = (const float*)d_in[19];
    float* out = (float*)d_out;

    zero_kernel<<<1024, 256>>>();

    // nf2 = (silu(x@nm_w1+b1)@nm_w2+b2) @ mm_w1_top   [N,128]
    node_kernel<<<NN / RT, H>>>(node_features, nm_w1, nm_b1, nm_w2, nm_b2, mm_w1);

    count_kernel<<<(EE + 255) / 256, 256>>>(edge_index);

    // fused edge pipeline + scatter
    edge_kernel<<<EE / RT, H>>>(edge_index, node_pos, grid_pos,
                                em_w1, em_b1, em_w2, em_b2,
                                mm_w1, mm_b1, mm_w2, mm_b2);

    // update MLP on mean-aggregated features
    update_kernel<<<GG / RT, H>>>(um_w1, um_b1, um_w2, um_b2, out);
}